// round 1
// baseline (speedup 1.0000x reference)
#include <cuda_runtime.h>

// Problem constants
// x:    [8, 8, 32, 64, 64]  (N, t0, z0, H0, W0)  fp32
// W:    [512, 32, 3, 3]     (T1*Z1, z0, K, K)
// bias: [512]
// out v: [8, 8, 64, 32, 32] (N, T1, Z1, H1, W1)
//
// Pipeline:
//  1) wt_kernel:   W -> g_wt[t1][k=ic*9+kh*3+kw][z]   (conv-friendly layout)
//  2) conv_kernel: u_hat -> g_u2[n][h][w][t0][t1][z]  (routing-friendly layout)
//  3) route<0>:    r = 1/8 uniform; p,v; b = sum_z u*v
//  4) pool_softmax: r = softmax_t1(maxpool3x3(b))
//  5) route<1>:    p,v; b += sum_z u*v
//  6) pool_softmax
//  7) route<2>:    p,v; write v to g_vs[n][h][w][t1*64+z]
//  8) transpose:   g_vs -> out[n][t1*64+z][h*32+w]

#define NB 8        // batch N
#define T0 8
#define T1C 8
#define Z1C 64
#define ICC 32
#define H0C 64
#define H1C 32

// Scratch (device globals; no allocation allowed)
__device__ __align__(128) float g_u2[8 * 32 * 32 * 8 * 8 * 64];   // 134 MB  [n][h][w][t0][t1][z]
__device__ __align__(128) float g_wt[8 * 288 * 64];               // [t1][k][z]
__device__ __align__(128) float g_b [8 * 8 * 32 * 32 * 8];        // [n][t0][h][w][t1]
__device__ __align__(128) float g_r [8 * 8 * 32 * 32 * 8];        // [n][t0][h][w][t1]
__device__ __align__(128) float g_vs[8 * 32 * 32 * 512];          // [n][h][w][t1*64+z]

// ---------------------------------------------------------------------------
// 1) Repack W: W[oc][ic][kh][kw] -> g_wt[(t1*288 + ic*9+kh*3+kw)*64 + z]
// ---------------------------------------------------------------------------
__global__ void wt_kernel(const float* __restrict__ W) {
    int idx = blockIdx.x * 256 + threadIdx.x;
    if (idx >= 512 * 288) return;
    int oc = idx / 288;
    int k  = idx % 288;
    g_wt[((oc >> 6) * 288 + k) * 64 + (oc & 63)] = W[idx];
}

// ---------------------------------------------------------------------------
// 2) Conv, stride 2, pad 1, 3x3.  Block: one image b=(n,t0), one t1 (64 oc),
//    4 output rows x 32 cols.  256 threads: tn=col (32), tm=oc-octet (8).
//    Each thread: 8 oc x 4 rows, accumulated as f32x2 pairs over adjacent oc.
// ---------------------------------------------------------------------------
__global__ __launch_bounds__(256) void conv_kernel(const float* __restrict__ x,
                                                   const float* __restrict__ bias) {
    __shared__ float sW[72 * 64];       // [k_local][z]
    __shared__ float sX[8 * 9 * 66];    // [icc][row][ Od(33) | Ev(33) ]

    const int tid = threadIdx.x;
    const int tn = tid & 31;            // output col
    const int tm = tid >> 5;            // oc octet (z = tm*8 .. tm*8+7)
    const int r0 = blockIdx.x * 4;      // output row base
    const int t1 = blockIdx.y;
    const int b  = blockIdx.z;          // n*8 + t0
    const int n  = b >> 3, t0 = b & 7;

    // accumulators: pair j covers z = tm*8 + 2j, 2j+1; rows rl=0..3
    unsigned long long acc[4][4];
#pragma unroll
    for (int j = 0; j < 4; j++) {
        float2 bb = *(const float2*)&bias[t1 * 64 + tm * 8 + 2 * j];
        unsigned long long pb;
        asm("mov.b64 %0, {%1, %2};" : "=l"(pb) : "f"(bb.x), "f"(bb.y));
#pragma unroll
        for (int rl = 0; rl < 4; rl++) acc[j][rl] = pb;
    }

    for (int ic0 = 0; ic0 < 32; ic0 += 8) {
        __syncthreads();
        // load W chunk: 72 x 64 floats, coalesced from g_wt
        {
            const float* src = g_wt + (t1 * 288 + ic0 * 9) * 64;
#pragma unroll
            for (int i = 0; i < 18; i++) sW[tid + 256 * i] = src[tid + 256 * i];
        }
        // load X chunk: 8 ic x 9 rows x cols g=-1..64, even/odd de-interleave
        for (int i = tid; i < 8 * 9 * 66; i += 256) {
            int g = i % 66 - 1;             // global input col, -1..64
            int rowi = i / 66;              // icc*9 + lr
            int lr = rowi % 9;
            int icc = rowi / 9;
            int gr = 2 * r0 - 1 + lr;       // global input row
            float v = 0.f;
            if (g >= 0 && g < 64 && gr >= 0)
                v = x[((b * 32 + ic0 + icc) * 64 + gr) * 64 + g];
            // odd g -> Od[(g+1)/2] at base+idx ; even g -> Ev[g/2] at base+33+idx
            int off = (g & 1) ? ((g + 1) >> 1) : (33 + (g >> 1));
            sX[rowi * 66 + off] = v;
        }
        __syncthreads();

#pragma unroll
        for (int icc = 0; icc < 8; icc++) {
#pragma unroll
            for (int kh = 0; kh < 3; kh++) {
#pragma unroll
                for (int kw = 0; kw < 3; kw++) {
                    const int kl = icc * 9 + kh * 3 + kw;
                    const float* wp = &sW[kl * 64 + tm * 8];
                    unsigned long long w0 = *(const unsigned long long*)(wp + 0);
                    unsigned long long w1 = *(const unsigned long long*)(wp + 2);
                    unsigned long long w2 = *(const unsigned long long*)(wp + 4);
                    unsigned long long w3 = *(const unsigned long long*)(wp + 6);
                    // input col: kw=0 -> Od[c]; kw=1 -> Ev[c]; kw=2 -> Od[c+1]
                    int coff = (kw == 0) ? tn : ((kw == 1) ? (33 + tn) : (tn + 1));
#pragma unroll
                    for (int rl = 0; rl < 4; rl++) {
                        float xv = sX[(icc * 9 + 2 * rl + kh) * 66 + coff];
                        unsigned long long xd;
                        asm("mov.b64 %0, {%1, %1};" : "=l"(xd) : "f"(xv));
                        asm("fma.rn.f32x2 %0, %1, %2, %0;" : "+l"(acc[0][rl]) : "l"(w0), "l"(xd));
                        asm("fma.rn.f32x2 %0, %1, %2, %0;" : "+l"(acc[1][rl]) : "l"(w1), "l"(xd));
                        asm("fma.rn.f32x2 %0, %1, %2, %0;" : "+l"(acc[2][rl]) : "l"(w2), "l"(xd));
                        asm("fma.rn.f32x2 %0, %1, %2, %0;" : "+l"(acc[3][rl]) : "l"(w3), "l"(xd));
                    }
                }
            }
        }
    }

    // epilogue: write u_hat in [n][h][w][t0][t1][z] layout, 2x float4 per row
#pragma unroll
    for (int rl = 0; rl < 4; rl++) {
        float f0, f1, f2, f3, f4, f5, f6, f7;
        asm("mov.b64 {%0, %1}, %2;" : "=f"(f0), "=f"(f1) : "l"(acc[0][rl]));
        asm("mov.b64 {%0, %1}, %2;" : "=f"(f2), "=f"(f3) : "l"(acc[1][rl]));
        asm("mov.b64 {%0, %1}, %2;" : "=f"(f4), "=f"(f5) : "l"(acc[2][rl]));
        asm("mov.b64 {%0, %1}, %2;" : "=f"(f6), "=f"(f7) : "l"(acc[3][rl]));
        int h = r0 + rl;
        float* dst = &g_u2[((((n * 32 + h) * 32 + tn) * 8 + t0) * 8 + t1) * 64 + tm * 8];
        *(float4*)(dst + 0) = make_float4(f0, f1, f2, f3);
        *(float4*)(dst + 4) = make_float4(f4, f5, f6, f7);
    }
}

// ---------------------------------------------------------------------------
// 3/5/7) Routing iteration.  One block per pixel (n,h,w), 128 threads.
//  MODE 0: r = 1/8, b  = sum_z u*v
//  MODE 1: r from g_r, b += sum_z u*v
//  MODE 2: r from g_r, write v to g_vs
// ---------------------------------------------------------------------------
template <int MODE>
__global__ __launch_bounds__(128) void route_kernel() {
    __shared__ float su[4096];   // [t0][t1][z]
    __shared__ float sr[64];     // [t0][t1]

    const int pix = blockIdx.x;          // (n*32+h)*32+w
    const int n = pix >> 10;
    const int hw = pix & 1023;
    const int tid = threadIdx.x;

    const float4* up = (const float4*)(g_u2 + (size_t)pix * 4096);
#pragma unroll
    for (int i = 0; i < 8; i++) ((float4*)su)[tid + 128 * i] = up[tid + 128 * i];
    if (MODE >= 1 && tid < 64) {
        int rt0 = tid >> 3, rt1 = tid & 7;
        sr[tid] = g_r[((n * 8 + rt0) * 1024 + hw) * 8 + rt1];
    }
    __syncthreads();

    // thread -> (t1, z-quad): 16 threads per t1 cover z=0..63 as float4s
    const int t1 = tid >> 4;
    const int z4 = tid & 15;

    float4 p = make_float4(0.f, 0.f, 0.f, 0.f);
#pragma unroll
    for (int t0 = 0; t0 < 8; t0++) {
        float r = (MODE == 0) ? 0.125f : sr[t0 * 8 + t1];
        float4 u = ((const float4*)su)[(t0 * 8 + t1) * 16 + z4];
        p.x += r * u.x; p.y += r * u.y; p.z += r * u.z; p.w += r * u.w;
    }
    float n2 = p.x * p.x + p.y * p.y + p.z * p.z + p.w * p.w;
#pragma unroll
    for (int m = 1; m < 16; m <<= 1) n2 += __shfl_xor_sync(0xffffffffu, n2, m);
    float s = n2 / (1.f + n2) * rsqrtf(n2 + 1e-9f);
    float4 v = make_float4(p.x * s, p.y * s, p.z * s, p.w * s);

    if (MODE == 2) {
        ((float4*)(g_vs + (size_t)pix * 512))[tid] = v;
    } else {
        // delta_b[t0][t1] = sum_z u[t0][t1][z] * v[t1][z]
        float d[8];
#pragma unroll
        for (int t0 = 0; t0 < 8; t0++) {
            float4 u = ((const float4*)su)[(t0 * 8 + t1) * 16 + z4];
            d[t0] = u.x * v.x + u.y * v.y + u.z * v.z + u.w * v.w;
        }
#pragma unroll
        for (int m = 1; m < 16; m <<= 1) {
#pragma unroll
            for (int t0 = 0; t0 < 8; t0++)
                d[t0] += __shfl_xor_sync(0xffffffffu, d[t0], m);
        }
        if ((tid & 15) == 0) {
#pragma unroll
            for (int t0 = 0; t0 < 8; t0++) {
                float* bp = &g_b[((n * 8 + t0) * 1024 + hw) * 8 + t1];
                if (MODE == 0) *bp = d[t0];
                else           *bp += d[t0];
            }
        }
    }
}

// ---------------------------------------------------------------------------
// 4/6) r = softmax_t1( maxpool3x3_same(b) ).  One block per (n,t0).
// ---------------------------------------------------------------------------
__global__ __launch_bounds__(256) void pool_softmax_kernel() {
    __shared__ float sb[8192];   // [h][w][t1]
    const int nt = blockIdx.x;   // n*8 + t0
    const int tid = threadIdx.x;

    const float4* src = (const float4*)(g_b + nt * 8192);
#pragma unroll
    for (int i = 0; i < 8; i++) ((float4*)sb)[tid + 256 * i] = src[tid + 256 * i];
    __syncthreads();

#pragma unroll
    for (int q = 0; q < 4; q++) {
        int pixel = tid + 256 * q;
        int h = pixel >> 5, w = pixel & 31;
        float m[8];
#pragma unroll
        for (int t = 0; t < 8; t++) m[t] = -3.4e38f;
#pragma unroll
        for (int dh = -1; dh <= 1; dh++) {
            int hh = h + dh;
            if (hh < 0 || hh > 31) continue;
#pragma unroll
            for (int dw = -1; dw <= 1; dw++) {
                int ww = w + dw;
                if (ww < 0 || ww > 31) continue;
                const float* pp = &sb[(hh * 32 + ww) * 8];
#pragma unroll
                for (int t = 0; t < 8; t++) m[t] = fmaxf(m[t], pp[t]);
            }
        }
        float mx = m[0];
#pragma unroll
        for (int t = 1; t < 8; t++) mx = fmaxf(mx, m[t]);
        float e[8], ssum = 0.f;
#pragma unroll
        for (int t = 0; t < 8; t++) { e[t] = expf(m[t] - mx); ssum += e[t]; }
        float inv = 1.f / ssum;
        float* dst = &g_r[nt * 8192 + pixel * 8];
        *(float4*)(dst + 0) = make_float4(e[0] * inv, e[1] * inv, e[2] * inv, e[3] * inv);
        *(float4*)(dst + 4) = make_float4(e[4] * inv, e[5] * inv, e[6] * inv, e[7] * inv);
    }
}

// ---------------------------------------------------------------------------
// 8) transpose g_vs [n][hw=1024][tz=512] -> out [n][tz=512][hw=1024]
// ---------------------------------------------------------------------------
__global__ __launch_bounds__(256) void transpose_kernel(float* __restrict__ out) {
    __shared__ float t[32][33];
    const int n = blockIdx.z;
    const int x0 = blockIdx.x * 32;   // tz tile
    const int y0 = blockIdx.y * 32;   // hw tile
    const int tx = threadIdx.x & 31;
    const int ty = threadIdx.x >> 5;  // 8 rows per pass
    const float* src = g_vs + (size_t)n * 1024 * 512;
    float* dst = out + (size_t)n * 512 * 1024;
#pragma unroll
    for (int i = 0; i < 4; i++) {
        int y = ty + i * 8;
        t[y][tx] = src[(y0 + y) * 512 + x0 + tx];
    }
    __syncthreads();
#pragma unroll
    for (int i = 0; i < 4; i++) {
        int y = ty + i * 8;
        dst[(x0 + y) * 1024 + y0 + tx] = t[tx][y];
    }
}

// ---------------------------------------------------------------------------
extern "C" void kernel_launch(void* const* d_in, const int* in_sizes, int n_in,
                              void* d_out, int out_size) {
    const float* x    = (const float*)d_in[0];
    const float* W    = (const float*)d_in[1];
    const float* bias = (const float*)d_in[2];
    float* out = (float*)d_out;

    wt_kernel<<<(512 * 288 + 255) / 256, 256>>>(W);

    dim3 cg(8, 8, 64);                 // row-groups, t1, image(n*8+t0)
    conv_kernel<<<cg, 256>>>(x, bias);

    route_kernel<0><<<8192, 128>>>();
    pool_softmax_kernel<<<64, 256>>>();
    route_kernel<1><<<8192, 128>>>();
    pool_softmax_kernel<<<64, 256>>>();
    route_kernel<2><<<8192, 128>>>();

    dim3 tg(16, 32, 8);
    transpose_kernel<<<tg, 256>>>(out);
}

// round 3
// speedup vs baseline: 2.4310x; 2.4310x over previous
#include <cuda_runtime.h>
#include <cstdint>

// CapsuleLayer: conv(stride2,3x3) via legacy mma.sync tf32 (sm_80+ PTX, works on
// plain sm_100 target), then 3x dynamic routing, then output transpose.
//
// x:    [8, 8, 32, 64, 64]  fp32      W: [512, 32, 3, 3]    bias: [512]
// out:  [8, 8, 64, 32, 32]  (N, T1, Z1, H1, W1) fp32

#define DEVINL __device__ __forceinline__

DEVINL uint32_t smem_u32(const void* p) {
    uint32_t a;
    asm("{ .reg .u64 t; cvta.to.shared.u64 t, %1; cvt.u32.u64 %0, t; }" : "=r"(a) : "l"(p));
    return a;
}
DEVINL void cp16(uint32_t dst, const void* src) {
    asm volatile("cp.async.cg.shared.global [%0], [%1], 16;" ::"r"(dst), "l"(src) : "memory");
}

// ---------------------------------------------------------------------------
// Device-global scratch (bss zero-init; pad ring of g_xt is never written)
// ---------------------------------------------------------------------------
__device__ __align__(128) float g_xt[64 * 66 * 66 * 32];        // NHWC padded, tf32
__device__ __align__(128) float g_w2[9 * 512 * 32];             // [kpos][oc][ic], tf32
__device__ __align__(128) float g_u2[8 * 32 * 32 * 8 * 8 * 64]; // [n][h][w][t0][t1][z]
__device__ __align__(128) float g_b [8 * 8 * 32 * 32 * 8];      // [n][t0][h][w][t1]
__device__ __align__(128) float g_r [8 * 8 * 32 * 32 * 8];
__device__ __align__(128) float g_vs[8 * 32 * 32 * 512];        // [n][h][w][t1*64+z]

// ---------------------------------------------------------------------------
// 1) x -> g_xt  (NCHW -> padded NHWC, tf32 rounding)
// ---------------------------------------------------------------------------
__global__ __launch_bounds__(256) void xt_kernel(const float* __restrict__ x) {
    __shared__ float s[64 * 33];
    const int b = blockIdx.y, h0 = blockIdx.x;
    const int t = threadIdx.x;
    const int lane = t & 31, icg = t >> 5;
    const float* xp = x + ((size_t)(b * 32) * 64 + h0) * 64;
#pragma unroll
    for (int i = 0; i < 4; i++) {
        int ic = icg + 8 * i;
        s[lane * 33 + ic]        = xp[(size_t)ic * 4096 + lane];
        s[(lane + 32) * 33 + ic] = xp[(size_t)ic * 4096 + lane + 32];
    }
    __syncthreads();
    uint32_t* dst = (uint32_t*)(g_xt + (((size_t)b * 66 + h0 + 1) * 66 + 1) * 32);
#pragma unroll
    for (int i = 0; i < 8; i++) {
        int idx = t + 256 * i;
        int w0 = idx >> 5, ic = idx & 31;
        uint32_t u;
        asm("cvt.rna.tf32.f32 %0, %1;" : "=r"(u) : "f"(s[w0 * 33 + ic]));
        dst[idx] = u;
    }
}

// ---------------------------------------------------------------------------
// 2) W -> g_w2 [kpos][oc][ic] tf32
// ---------------------------------------------------------------------------
__global__ void w2_kernel(const float* __restrict__ W) {
    int idx = blockIdx.x * 256 + threadIdx.x;   // oc*288 + ic*9 + kp
    if (idx >= 512 * 288) return;
    int oc = idx / 288, r = idx % 288, ic = r / 9, kp = r % 9;
    uint32_t u;
    asm("cvt.rna.tf32.f32 %0, %1;" : "=r"(u) : "f"(W[idx]));
    ((uint32_t*)g_w2)[((size_t)kp * 512 + oc) * 32 + ic] = u;
}

// ---------------------------------------------------------------------------
// 3) conv via mma.sync tf32: D[oc=128][px=128] = sum_{9 kpos, 32 ic} W·X
//    grid (ptile=8, m=4, b=64), 256 threads, 2 CTAs/SM, double-buffered.
//    smem tiles: row stride 36 floats (144B, 16B aligned, conflict-free frags)
// ---------------------------------------------------------------------------
#define TSTRIDE 36
#define TILE_F  (128 * TSTRIDE)   // floats per tile (A or B)

__global__ __launch_bounds__(256, 2) void conv_mma_kernel(const float* __restrict__ bias) {
    extern __shared__ float dsm[];
    const uint32_t sbase = smem_u32(dsm);
    // buffers: [buf][A|B]
    const uint32_t offA[2] = {0u, 2u * TILE_F * 4u};
    const uint32_t offB[2] = {TILE_F * 4u, 3u * TILE_F * 4u};

    const int tid = threadIdx.x;
    const int wid = tid >> 5, lane = tid & 31;
    const int gid = lane >> 2, tig = lane & 3;   // mma groupID / thread-in-group

    const int pt = blockIdx.x;    // pixel tile (4 output rows)
    const int m  = blockIdx.y;    // oc block of 128
    const int b  = blockIdx.z;    // n*8 + t0
    const int h0 = pt * 4;

    // warp tile: 64 oc x 32 px
    const int m0 = (wid & 1) * 64;
    const int n0 = (wid >> 1) * 32;

    float acc[4][4][4];
#pragma unroll
    for (int mi = 0; mi < 4; mi++)
#pragma unroll
        for (int ni = 0; ni < 4; ni++)
#pragma unroll
            for (int j = 0; j < 4; j++) acc[mi][ni][j] = 0.f;

    // stage-issue lambda (manual): s in 0..8
    auto issue = [&](int s, int buf) {
        const int kh = s / 3, kw = s % 3;
        const float4* Asrc = (const float4*)g_w2 + ((size_t)s * 512 + m * 128) * 8;
        const int ihb = 2 * h0 + kh;
#pragma unroll
        for (int i = 0; i < 4; i++) {
            int c = tid + 256 * i;
            int o = c >> 3, q = c & 7;
            cp16(sbase + offA[buf] + (o * TSTRIDE + q * 4) * 4, Asrc + c);
            int hl = o >> 5, wl = o & 31;
            const float4* src =
                (const float4*)g_xt + (((size_t)b * 66 + ihb + 2 * hl) * 66 + 2 * wl + kw) * 8 + q;
            cp16(sbase + offB[buf] + (o * TSTRIDE + q * 4) * 4, src);
        }
        asm volatile("cp.async.commit_group;");
    };

    issue(0, 0);

    for (int s = 0; s < 9; s++) {
        if (s < 8) {
            issue(s + 1, (s + 1) & 1);
            asm volatile("cp.async.wait_group 1;" ::: "memory");
        } else {
            asm volatile("cp.async.wait_group 0;" ::: "memory");
        }
        __syncthreads();

        const uint32_t* sA = (const uint32_t*)dsm + offA[s & 1] / 4;
        const uint32_t* sB = (const uint32_t*)dsm + offB[s & 1] / 4;

#pragma unroll
        for (int kk = 0; kk < 4; kk++) {
            const int kc = kk * 8 + tig;
            uint32_t a[4][4];
#pragma unroll
            for (int mi = 0; mi < 4; mi++) {
                int r = m0 + mi * 16 + gid;
                a[mi][0] = sA[r * TSTRIDE + kc];
                a[mi][1] = sA[(r + 8) * TSTRIDE + kc];
                a[mi][2] = sA[r * TSTRIDE + kc + 4];
                a[mi][3] = sA[(r + 8) * TSTRIDE + kc + 4];
            }
            uint32_t bf[4][2];
#pragma unroll
            for (int ni = 0; ni < 4; ni++) {
                int cn = n0 + ni * 8 + gid;
                bf[ni][0] = sB[cn * TSTRIDE + kc];
                bf[ni][1] = sB[cn * TSTRIDE + kc + 4];
            }
#pragma unroll
            for (int mi = 0; mi < 4; mi++)
#pragma unroll
                for (int ni = 0; ni < 4; ni++)
                    asm volatile(
                        "mma.sync.aligned.m16n8k8.row.col.f32.tf32.tf32.f32 "
                        "{%0,%1,%2,%3}, {%4,%5,%6,%7}, {%8,%9}, {%0,%1,%2,%3};"
                        : "+f"(acc[mi][ni][0]), "+f"(acc[mi][ni][1]),
                          "+f"(acc[mi][ni][2]), "+f"(acc[mi][ni][3])
                        : "r"(a[mi][0]), "r"(a[mi][1]), "r"(a[mi][2]), "r"(a[mi][3]),
                          "r"(bf[ni][0]), "r"(bf[ni][1]));
        }
        __syncthreads();
    }

    // Epilogue: regs -> stage[px][oc] (+bias) -> g_u2, row stride 132 floats
    float* stage = dsm;
#pragma unroll
    for (int mi = 0; mi < 4; mi++) {
        int r = m0 + mi * 16 + gid;
        float bi0 = bias[m * 128 + r];
        float bi1 = bias[m * 128 + r + 8];
#pragma unroll
        for (int ni = 0; ni < 4; ni++) {
            int cn = n0 + ni * 8 + 2 * tig;
            stage[cn * 132 + r]           = acc[mi][ni][0] + bi0;
            stage[(cn + 1) * 132 + r]     = acc[mi][ni][1] + bi0;
            stage[cn * 132 + r + 8]       = acc[mi][ni][2] + bi1;
            stage[(cn + 1) * 132 + r + 8] = acc[mi][ni][3] + bi1;
        }
    }
    __syncthreads();

    const int n = b >> 3, t0 = b & 7;
#pragma unroll
    for (int k = 0; k < 16; k++) {
        int idx = tid + 256 * k;        // 4096 float4s = 128 px * 32
        int p = idx >> 5, q = idx & 31;
        int h = h0 + (p >> 5), w = p & 31;
        float4 v = *(const float4*)(stage + p * 132 + q * 4);
        size_t off = ((((size_t)(n * 32 + h) * 32 + w) * 8 + t0) * 512) + m * 128 + q * 4;
        *(float4*)(g_u2 + off) = v;
    }
}

// ---------------------------------------------------------------------------
// 4) Routing iteration. One block per pixel (n,h,w), 128 threads.
// ---------------------------------------------------------------------------
template <int MODE>
__global__ __launch_bounds__(128) void route_kernel() {
    __shared__ float su[4096];
    __shared__ float sr[64];

    const int pix = blockIdx.x;
    const int n = pix >> 10;
    const int hw = pix & 1023;
    const int tid = threadIdx.x;

    const float4* up = (const float4*)(g_u2 + (size_t)pix * 4096);
#pragma unroll
    for (int i = 0; i < 8; i++) ((float4*)su)[tid + 128 * i] = up[tid + 128 * i];
    if (MODE >= 1 && tid < 64) {
        int rt0 = tid >> 3, rt1 = tid & 7;
        sr[tid] = g_r[((n * 8 + rt0) * 1024 + hw) * 8 + rt1];
    }
    __syncthreads();

    const int t1 = tid >> 4;
    const int z4 = tid & 15;

    float4 p = make_float4(0.f, 0.f, 0.f, 0.f);
#pragma unroll
    for (int t0 = 0; t0 < 8; t0++) {
        float r = (MODE == 0) ? 0.125f : sr[t0 * 8 + t1];
        float4 u = ((const float4*)su)[(t0 * 8 + t1) * 16 + z4];
        p.x += r * u.x; p.y += r * u.y; p.z += r * u.z; p.w += r * u.w;
    }
    float n2 = p.x * p.x + p.y * p.y + p.z * p.z + p.w * p.w;
#pragma unroll
    for (int mm = 1; mm < 16; mm <<= 1) n2 += __shfl_xor_sync(0xffffffffu, n2, mm);
    float s = n2 / (1.f + n2) * rsqrtf(n2 + 1e-9f);
    float4 v = make_float4(p.x * s, p.y * s, p.z * s, p.w * s);

    if (MODE == 2) {
        ((float4*)(g_vs + (size_t)pix * 512))[tid] = v;
    } else {
        float d[8];
#pragma unroll
        for (int t0 = 0; t0 < 8; t0++) {
            float4 u = ((const float4*)su)[(t0 * 8 + t1) * 16 + z4];
            d[t0] = u.x * v.x + u.y * v.y + u.z * v.z + u.w * v.w;
        }
#pragma unroll
        for (int mm = 1; mm < 16; mm <<= 1) {
#pragma unroll
            for (int t0 = 0; t0 < 8; t0++)
                d[t0] += __shfl_xor_sync(0xffffffffu, d[t0], mm);
        }
        if ((tid & 15) == 0) {
#pragma unroll
            for (int t0 = 0; t0 < 8; t0++) {
                float* bp = &g_b[((n * 8 + t0) * 1024 + hw) * 8 + t1];
                if (MODE == 0) *bp = d[t0];
                else           *bp += d[t0];
            }
        }
    }
}

// ---------------------------------------------------------------------------
// 5) r = softmax_t1( maxpool3x3_same(b) ), one block per (n,t0)
// ---------------------------------------------------------------------------
__global__ __launch_bounds__(256) void pool_softmax_kernel() {
    __shared__ float sbuf[8192];
    const int nt = blockIdx.x;
    const int tid = threadIdx.x;

    const float4* src = (const float4*)(g_b + nt * 8192);
#pragma unroll
    for (int i = 0; i < 8; i++) ((float4*)sbuf)[tid + 256 * i] = src[tid + 256 * i];
    __syncthreads();

#pragma unroll
    for (int q = 0; q < 4; q++) {
        int pixel = tid + 256 * q;
        int h = pixel >> 5, w = pixel & 31;
        float m[8];
#pragma unroll
        for (int t = 0; t < 8; t++) m[t] = -3.4e38f;
#pragma unroll
        for (int dh = -1; dh <= 1; dh++) {
            int hh = h + dh;
            if (hh < 0 || hh > 31) continue;
#pragma unroll
            for (int dw = -1; dw <= 1; dw++) {
                int ww = w + dw;
                if (ww < 0 || ww > 31) continue;
                const float* pp = &sbuf[(hh * 32 + ww) * 8];
#pragma unroll
                for (int t = 0; t < 8; t++) m[t] = fmaxf(m[t], pp[t]);
            }
        }
        float mx = m[0];
#pragma unroll
        for (int t = 1; t < 8; t++) mx = fmaxf(mx, m[t]);
        float e[8], ssum = 0.f;
#pragma unroll
        for (int t = 0; t < 8; t++) { e[t] = expf(m[t] - mx); ssum += e[t]; }
        float inv = 1.f / ssum;
        float* dst = &g_r[nt * 8192 + pixel * 8];
        *(float4*)(dst + 0) = make_float4(e[0] * inv, e[1] * inv, e[2] * inv, e[3] * inv);
        *(float4*)(dst + 4) = make_float4(e[4] * inv, e[5] * inv, e[6] * inv, e[7] * inv);
    }
}

// ---------------------------------------------------------------------------
// 6) transpose g_vs [n][hw][tz] -> out [n][tz][hw]
// ---------------------------------------------------------------------------
__global__ __launch_bounds__(256) void transpose_kernel(float* __restrict__ out) {
    __shared__ float t[32][33];
    const int n = blockIdx.z;
    const int x0 = blockIdx.x * 32;
    const int y0 = blockIdx.y * 32;
    const int tx = threadIdx.x & 31;
    const int ty = threadIdx.x >> 5;
    const float* src = g_vs + (size_t)n * 1024 * 512;
    float* dst = out + (size_t)n * 512 * 1024;
#pragma unroll
    for (int i = 0; i < 4; i++) {
        int y = ty + i * 8;
        t[y][tx] = src[(y0 + y) * 512 + x0 + tx];
    }
    __syncthreads();
#pragma unroll
    for (int i = 0; i < 4; i++) {
        int y = ty + i * 8;
        dst[(x0 + y) * 1024 + y0 + tx] = t[tx][y];
    }
}

// ---------------------------------------------------------------------------
extern "C" void kernel_launch(void* const* d_in, const int* in_sizes, int n_in,
                              void* d_out, int out_size) {
    const float* x    = (const float*)d_in[0];
    const float* W    = (const float*)d_in[1];
    const float* bias = (const float*)d_in[2];
    float* out = (float*)d_out;

    static bool attr_done = false;
    if (!attr_done) {
        cudaFuncSetAttribute(conv_mma_kernel,
                             cudaFuncAttributeMaxDynamicSharedMemorySize, 4 * TILE_F * 4);
        attr_done = true;
    }

    xt_kernel<<<dim3(64, 64), 256>>>(x);
    w2_kernel<<<576, 256>>>(W);
    conv_mma_kernel<<<dim3(8, 4, 64), 256, 4 * TILE_F * 4>>>(bias);

    route_kernel<0><<<8192, 128>>>();
    pool_softmax_kernel<<<64, 256>>>();
    route_kernel<1><<<8192, 128>>>();
    pool_softmax_kernel<<<64, 256>>>();
    route_kernel<2><<<8192, 128>>>();

    dim3 tg(16, 32, 8);
    transpose_kernel<<<tg, 256>>>(out);
}